// round 4
// baseline (speedup 1.0000x reference)
#include <cuda_runtime.h>
#include <math.h>

#define NN 50000
#define EE 800000
#define DD 128
#define HH 32
#define JP (HH / 2)          // 16 j-pairs per matrix

#define SCAN_T 1024
#define NBLK ((NN + SCAN_T - 1) / SCAN_T)   // 49

// ---------------- scratch (__device__ globals; no allocation) ----------------
__device__ int   g_deg[NN];
__device__ int   g_off[NN];
__device__ int   g_fill[NN];
__device__ int   g_srcs[EE];        // src node per CSR slot (grouped by dst)
__device__ int   g_bsum[NBLK];
__device__ unsigned long long g_pwl[DD * JP];  // packed W1_l: [k][jp] = {W[2jp][k], W[2jp+1][k]}
__device__ unsigned long long g_pwr[DD * JP];  // packed W1_r
__device__ float g_y[NN * HH];      // x @ W1_l^T
__device__ float g_r[NN * HH];      // x @ W1_r^T
__device__ float g_s[NN];           // h . W2_l
__device__ float g_t[NN];           // h . W2_r

// ---------------- packed f32x2 helpers ----------------
__device__ __forceinline__ void fma2(unsigned long long& d,
                                     unsigned long long a,
                                     unsigned long long b) {
    asm("fma.rn.f32x2 %0, %1, %2, %0;" : "+l"(d) : "l"(a), "l"(b));
}
__device__ __forceinline__ unsigned long long bcast2(float v) {
    unsigned long long r;
    unsigned int u = __float_as_uint(v);
    asm("mov.b64 %0, {%1, %1};" : "=l"(r) : "r"(u));
    return r;
}
__device__ __forceinline__ float lo2(unsigned long long v) {
    return __uint_as_float((unsigned int)(v & 0xFFFFFFFFull));
}
__device__ __forceinline__ float hi2(unsigned long long v) {
    return __uint_as_float((unsigned int)(v >> 32));
}

// ---------------- per-block dtype sniff for edge_index ----------------
// int64 indices are all < 50000 -> high u32 of each u64 word always 0.
// int32 layout packs two indices per u64 -> some high u32 nonzero
// (P[all 256 high-halves == 0] ~ (2e-5)^256 ~ 0).
// Reads the same 2KB from every block -> L2-resident, effectively free.
__device__ __forceinline__ int sniff_mode32(const void* ei, int tid) {
    __shared__ int s_flag;
    if (tid == 0) s_flag = 0;
    __syncthreads();
    if (tid < 256) {
        unsigned long long v = ((const unsigned long long*)ei)[tid];
        if (v > 0xFFFFFFFFull) atomicOr(&s_flag, 1);
    }
    __syncthreads();
    return s_flag;
}

__device__ __forceinline__ int load_idx(const void* ei, int mode32, int row, int e) {
    if (mode32) return ((const int*)ei)[(size_t)row * EE + e];
    return (int)(((const long long*)ei)[(size_t)row * EE + e]);
}

// ---------------- setup: pack weights (blocks 0..7) + zero degrees ----------
// blockDim = 256. Blocks [0,8): pack DD*JP=2048 u64 pairs. Blocks [8,...): zero g_deg.
__global__ void k_setup(const float* __restrict__ W1l, const float* __restrict__ W1r) {
    int b = blockIdx.x;
    if (b < 8) {
        int idx = b * 256 + threadIdx.x;      // 0..2047
        int k  = idx >> 4;                    // 0..127
        int jp = idx & (JP - 1);              // 0..15
        unsigned int l0 = __float_as_uint(W1l[(2 * jp + 0) * DD + k]);
        unsigned int l1 = __float_as_uint(W1l[(2 * jp + 1) * DD + k]);
        unsigned int r0 = __float_as_uint(W1r[(2 * jp + 0) * DD + k]);
        unsigned int r1 = __float_as_uint(W1r[(2 * jp + 1) * DD + k]);
        g_pwl[idx] = ((unsigned long long)l1 << 32) | l0;
        g_pwr[idx] = ((unsigned long long)r1 << 32) | r0;
    } else {
        int i = (b - 8) * 256 + threadIdx.x;
        if (i < NN) g_deg[i] = 0;
    }
}

// ---------------- CSR build ----------------
__global__ void k_deg(const void* __restrict__ ei) {
    int mode = sniff_mode32(ei, threadIdx.x);
    int e = blockIdx.x * blockDim.x + threadIdx.x;
    if (e >= EE) return;
    int d = load_idx(ei, mode, 1, e);
    atomicAdd(&g_deg[d], 1);
}

__global__ void k_scan_block() {
    __shared__ int sh[SCAN_T];
    int gid = blockIdx.x * SCAN_T + threadIdx.x;
    int v = (gid < NN) ? g_deg[gid] : 0;
    sh[threadIdx.x] = v;
    __syncthreads();
    #pragma unroll
    for (int off = 1; off < SCAN_T; off <<= 1) {
        int add = (threadIdx.x >= off) ? sh[threadIdx.x - off] : 0;
        __syncthreads();
        sh[threadIdx.x] += add;
        __syncthreads();
    }
    if (gid < NN) g_off[gid] = sh[threadIdx.x] - v;   // exclusive within block
    if (threadIdx.x == SCAN_T - 1) g_bsum[blockIdx.x] = sh[threadIdx.x];
}

// absorbs the top-level (49-entry) scan: every block loads g_bsum into smem
// and each thread computes the prefix for its scan-block id (<=49 adds).
__global__ void k_scan_add_fill() {
    __shared__ int s_bsum[NBLK];
    if (threadIdx.x < NBLK) s_bsum[threadIdx.x] = g_bsum[threadIdx.x];
    __syncthreads();
    int i = blockIdx.x * blockDim.x + threadIdx.x;
    if (i < NN) {
        int sb = i / SCAN_T;
        int pre = 0;
        for (int b = 0; b < sb; b++) pre += s_bsum[b];
        int o = g_off[i] + pre;
        g_off[i] = o;
        g_fill[i] = o;
    }
}

__global__ void k_bucket(const void* __restrict__ ei) {
    int mode = sniff_mode32(ei, threadIdx.x);
    int e = blockIdx.x * blockDim.x + threadIdx.x;
    if (e >= EE) return;
    int s = load_idx(ei, mode, 0, e);
    int d = load_idx(ei, mode, 1, e);
    int pos = atomicAdd(&g_fill[d], 1);
    g_srcs[pos] = s;
}

// ---------------- GEMM1: y = x @ W1_l^T, r = x @ W1_r^T (FFMA2 path) --------
__global__ void __launch_bounds__(256) k_gemm1(const float* __restrict__ x) {
    __shared__ unsigned long long sWl[DD * JP];   // 16 KB
    __shared__ unsigned long long sWr[DD * JP];   // 16 KB
    int tid = threadIdx.x;
    for (int i = tid; i < DD * JP; i += blockDim.x) {
        sWl[i] = g_pwl[i];
        sWr[i] = g_pwr[i];
    }
    __syncthreads();
    int n = blockIdx.x * blockDim.x + tid;
    if (n >= NN) return;

    unsigned long long accl[JP], accr[JP];
    #pragma unroll
    for (int j = 0; j < JP; j++) { accl[j] = 0ull; accr[j] = 0ull; }

    const float4* xr = (const float4*)(x + (size_t)n * DD);
    #pragma unroll 2
    for (int kk = 0; kk < DD / 4; kk++) {
        float4 xv = xr[kk];
        #pragma unroll
        for (int q = 0; q < 4; q++) {
            float xk = (q == 0) ? xv.x : (q == 1) ? xv.y : (q == 2) ? xv.z : xv.w;
            unsigned long long xx = bcast2(xk);
            int k = kk * 4 + q;
            const ulonglong2* wl2 = (const ulonglong2*)&sWl[k * JP];
            const ulonglong2* wr2 = (const ulonglong2*)&sWr[k * JP];
            #pragma unroll
            for (int p = 0; p < JP / 2; p++) {
                ulonglong2 wl = wl2[p];
                fma2(accl[2 * p + 0], xx, wl.x);
                fma2(accl[2 * p + 1], xx, wl.y);
                ulonglong2 wr = wr2[p];
                fma2(accr[2 * p + 0], xx, wr.x);
                fma2(accr[2 * p + 1], xx, wr.y);
            }
        }
    }
    float4* yo = (float4*)(g_y + (size_t)n * HH);
    float4* ro = (float4*)(g_r + (size_t)n * HH);
    #pragma unroll
    for (int p = 0; p < HH / 4; p++) {
        yo[p] = make_float4(lo2(accl[2*p]), hi2(accl[2*p]), lo2(accl[2*p+1]), hi2(accl[2*p+1]));
        ro[p] = make_float4(lo2(accr[2*p]), hi2(accr[2*p]), lo2(accr[2*p+1]), hi2(accr[2*p+1]));
    }
}

// ---------------- layer-1 aggregate + finalize + layer-2 dots ----------------
// warp per node; lane = feature. Neighbor loop unrolled x4 for MLP=4.
__global__ void k_agg1(const float* __restrict__ b1,
                       const float* __restrict__ W2l,
                       const float* __restrict__ W2r) {
    int gtid = blockIdx.x * blockDim.x + threadIdx.x;
    int n = gtid >> 5;
    int lane = threadIdx.x & 31;
    if (n >= NN) return;
    int beg = g_off[n];
    int dg  = g_deg[n];
    float a0 = 0.f, a1 = 0.f, a2 = 0.f, a3 = 0.f;
    int i = 0;
    for (; i + 4 <= dg; i += 4) {
        int s0 = __ldg(&g_srcs[beg + i + 0]);
        int s1 = __ldg(&g_srcs[beg + i + 1]);
        int s2 = __ldg(&g_srcs[beg + i + 2]);
        int s3 = __ldg(&g_srcs[beg + i + 3]);
        a0 += __ldg(&g_y[(size_t)s0 * HH + lane]);
        a1 += __ldg(&g_y[(size_t)s1 * HH + lane]);
        a2 += __ldg(&g_y[(size_t)s2 * HH + lane]);
        a3 += __ldg(&g_y[(size_t)s3 * HH + lane]);
    }
    for (; i < dg; i++) {
        int src = __ldg(&g_srcs[beg + i]);
        a0 += __ldg(&g_y[(size_t)src * HH + lane]);
    }
    float acc = (a0 + a1) + (a2 + a3);
    float inv = 1.f / (float)max(dg, 1);
    float h = acc * inv + b1[lane] + g_r[(size_t)n * HH + lane];
    h = fmaxf(h, 0.f);
    float sl = h * W2l[lane];
    float tl = h * W2r[lane];
    #pragma unroll
    for (int o = 16; o > 0; o >>= 1) {
        sl += __shfl_xor_sync(0xffffffffu, sl, o);
        tl += __shfl_xor_sync(0xffffffffu, tl, o);
    }
    if (lane == 0) { g_s[n] = sl; g_t[n] = tl; }
}

// ---------------- layer-2 scalar aggregate + sigmoid ----------------
__global__ void k_agg2(const float* __restrict__ b2, float* __restrict__ out) {
    int gtid = blockIdx.x * blockDim.x + threadIdx.x;
    int n = gtid >> 5;
    int lane = threadIdx.x & 31;
    if (n >= NN) return;
    int beg = g_off[n];
    int dg  = g_deg[n];
    float a0 = 0.f, a1 = 0.f;
    int i = lane;
    for (; i + 32 < dg; i += 64) {
        a0 += __ldg(&g_s[__ldg(&g_srcs[beg + i])]);
        a1 += __ldg(&g_s[__ldg(&g_srcs[beg + i + 32])]);
    }
    if (i < dg) a0 += __ldg(&g_s[__ldg(&g_srcs[beg + i])]);
    float acc = a0 + a1;
    #pragma unroll
    for (int o = 16; o > 0; o >>= 1) acc += __shfl_xor_sync(0xffffffffu, acc, o);
    if (lane == 0) {
        float z = acc / (float)max(dg, 1) + b2[0] + g_t[n];
        out[n] = 1.f / (1.f + expf(-z));
    }
}

// ---------------- launch ----------------
extern "C" void kernel_launch(void* const* d_in, const int* in_sizes, int n_in,
                              void* d_out, int out_size) {
    const float* x   = (const float*)d_in[0];
    const void*  ei  = d_in[1];               // int64 or int32, sniffed on device
    const float* W1l = (const float*)d_in[2];
    const float* b1  = (const float*)d_in[3];
    const float* W1r = (const float*)d_in[4];
    const float* W2l = (const float*)d_in[5];
    const float* b2  = (const float*)d_in[6];
    const float* W2r = (const float*)d_in[7];
    float* out = (float*)d_out;

    const int T = 256;
    k_setup<<<8 + (NN + T - 1) / T, T>>>(W1l, W1r);
    k_deg<<<(EE + T - 1) / T, T>>>(ei);
    k_scan_block<<<NBLK, SCAN_T>>>();
    k_scan_add_fill<<<(NN + T - 1) / T, T>>>();
    k_bucket<<<(EE + T - 1) / T, T>>>(ei);
    k_gemm1<<<(NN + T - 1) / T, T>>>(x);
    k_agg1<<<(NN * 32 + T - 1) / T, T>>>(b1, W2l, W2r);
    k_agg2<<<(NN * 32 + T - 1) / T, T>>>(b2, out);
}